// round 4
// baseline (speedup 1.0000x reference)
#include <cuda_runtime.h>

typedef unsigned long long ull;

// ---------------- device scratch (no runtime allocation allowed) ----------------
__device__ float  gS[32 * 64 * 9];     // strided sums for cond conv
__device__ float  gDw[32 * 576];       // per-sample depthwise weights
__device__ float  gPw[32 * 4096];      // per-sample pointwise weights, TRANSPOSED:
                                       //   gPw[b*4096 + c2*128 + o*2 + (c&1)]
__device__ float  gDb[32 * 64];        // per-sample dynamic bias
__device__ double gSum[64], gSumSq[64];// BN statistics accumulators
__device__ float  gScale[64], gShift[64];

// =================================================================================
// Kernel 0: zero stats (graph replays must be deterministic)
// =================================================================================
__global__ void k_zero() {
    int t = threadIdx.x;
    if (t < 64) { gSum[t] = 0.0; gSumSq[t] = 0.0; }
}

// =================================================================================
// Kernel 1: per-(b,c) 9 strided sums S[kh][kw] = sum_{oh,ow} x[2oh+kh, 2ow+kw]
// =================================================================================
__global__ void __launch_bounds__(256) k_cond_sums(const float* __restrict__ x) {
    int bc = blockIdx.x;                 // b*64 + c
    int t  = threadIdx.x;
    const float* base = x + (size_t)bc * 16384;

    int i  = t >> 1;                     // row 0..127
    int j0 = (t & 1) * 64;               // half-row
    const float4* row4 = (const float4*)(base + i * 128 + j0);

    float ca0 = 0.f, ca1 = 0.f, ca2 = 0.f;
#pragma unroll
    for (int k = 0; k < 16; k++) {
        float4 v = row4[k];
        int j = j0 + 4 * k;
        ca0 += v.x + ((j <= 122) ? v.z : 0.f);
        ca1 += v.y + ((j <= 122) ? v.w : 0.f);
        ca2 += ((j >= 2) ? v.x : 0.f) + v.z;
    }
    bool ev = ((i & 1) == 0);
    float f0 = (ev  && i <= 124) ? 1.f : 0.f;
    float f1 = (!ev && i <= 125) ? 1.f : 0.f;
    float f2 = (ev  && i >= 2)   ? 1.f : 0.f;

    float bins[9] = { f0*ca0, f0*ca1, f0*ca2,
                      f1*ca0, f1*ca1, f1*ca2,
                      f2*ca0, f2*ca1, f2*ca2 };
#pragma unroll
    for (int off = 16; off; off >>= 1)
#pragma unroll
        for (int k = 0; k < 9; k++)
            bins[k] += __shfl_down_sync(0xffffffffu, bins[k], off);

    __shared__ float red[8][9];
    int lane = t & 31, w = t >> 5;
    if (lane == 0)
#pragma unroll
        for (int k = 0; k < 9; k++) red[w][k] = bins[k];
    __syncthreads();
    if (t < 9) {
        float s = 0.f;
#pragma unroll
        for (int ww = 0; ww < 8; ww++) s += red[ww][t];
        gS[bc * 9 + t] = s;
    }
}

// =================================================================================
// Kernel 2: per-sample condition vector + dynamic weight generation (tiny GEMMs)
// =================================================================================
__global__ void __launch_bounds__(256) k_gen(
    const float* __restrict__ cg_w1, const float* __restrict__ cg_b1,
    const float* __restrict__ cg_w2, const float* __restrict__ cg_b2,
    const float* __restrict__ wg_w,  const float* __restrict__ wg_b,
    const float* __restrict__ pg_w,  const float* __restrict__ pg_b,
    const float* __restrict__ bg_w,  const float* __restrict__ bg_b)
{
    __shared__ float Ss[576];
    __shared__ float parts[256];
    __shared__ float c0[16];
    __shared__ float cond[16];

    int b = blockIdx.x;
    int t = threadIdx.x;

    for (int idx = t; idx < 576; idx += 256) Ss[idx] = gS[b * 576 + idx];
    __syncthreads();

    {
        int co = t >> 4, part = t & 15;
        const float* wrow = cg_w1 + co * 576 + part * 36;
        const float* srow = Ss + part * 36;
        float s = 0.f;
#pragma unroll
        for (int k = 0; k < 36; k++) s += wrow[k] * srow[k];
        parts[t] = s;
    }
    __syncthreads();
    if (t < 16) {
        float s = 0.f;
#pragma unroll
        for (int p = 0; p < 16; p++) s += parts[t * 16 + p];
        s = s * (1.0f / 3969.0f) + cg_b1[t];
        c0[t] = fmaxf(s, 0.f);
    }
    __syncthreads();
    if (t < 16) {
        float s = cg_b2[t];
#pragma unroll
        for (int i = 0; i < 16; i++) s += c0[i] * cg_w2[t * 16 + i];
        cond[t] = fmaxf(s, 0.f);
    }
    __syncthreads();

    for (int r = t; r < 576; r += 256) {
        float s = wg_b[r];
        const float* wr = wg_w + r * 16;
#pragma unroll
        for (int q = 0; q < 16; q++) s += cond[q] * wr[q];
        gDw[b * 576 + r] = fmaxf(s, 0.f);
    }
    // pointwise weights, stored TRANSPOSED-PAIRED: gPw[b][c2][o][c&1]
    for (int r = t; r < 4096; r += 256) {
        float s = pg_b[r];
        const float* wr = pg_w + r * 16;
#pragma unroll
        for (int q = 0; q < 16; q++) s += cond[q] * wr[q];
        int o = r >> 6, c = r & 63;
        gPw[b * 4096 + (c >> 1) * 128 + o * 2 + (c & 1)] = fmaxf(s, 0.f);
    }
    if (t < 64) {
        float s = bg_b[t];
        const float* wr = bg_w + t * 16;
#pragma unroll
        for (int q = 0; q < 16; q++) s += cond[q] * wr[q];
        gDb[b * 64 + t] = s;
    }
}

// =================================================================================
// Kernel 3: fused depthwise3x3 (global->regs, shuffle halo) + pointwise(64x64)
//   c-pair-split f32x2 pointwise with transposed pw (LDS.128 broadcasts);
//   one block per (h, b); 256 threads; 4 CTAs/SM.
// smem (floats):
//   ys2 [32 c2][128 w] float2-interleaved  offset 0      (8192)
//   pwT [32 c2][64 o]  u64 pairs            offset 8192   (4096)
//   dws [576]                               offset 12288
//   dbs [64]                                offset 12864
//   sst [128]  (s[64], s2[64])              offset 12928  -> 13056 fl = 52224 B
// =================================================================================
__global__ void __launch_bounds__(256, 4) k_main(const float* __restrict__ x,
                                                 float* __restrict__ out)
{
    extern __shared__ float sm[];
    float* ys2 = sm;
    float* pwT = sm + 8192;
    float* dws = sm + 12288;
    float* dbs = sm + 12864;
    float* sst = sm + 12928;

    int tid  = threadIdx.x;
    int lane = tid & 31, wid = tid >> 5;
    int h = blockIdx.x, b = blockIdx.y;

    // ---- stage per-sample dynamic weights into smem (already transposed) ----
    {
        const float4* pwg = (const float4*)(gPw + b * 4096);
        float4* pw4 = (float4*)pwT;
#pragma unroll
        for (int k = 0; k < 4; k++) pw4[tid + 256 * k] = pwg[tid + 256 * k];
        for (int idx = tid; idx < 576; idx += 256) dws[idx] = gDw[b * 576 + idx];
        if (tid < 64) dbs[tid] = gDb[b * 64 + tid];
        if (tid < 128) sst[tid] = 0.f;
    }
    __syncthreads();

    // ---- depthwise 3x3 (pad=1) straight from global; warp w: channels [8w,8w+8) ----
    const float4* xb = (const float4*)(x + (size_t)b * 64 * 16384);
    const float4 z4 = make_float4(0.f, 0.f, 0.f, 0.f);
    bool hasT = (h >= 1), hasB = (h <= 126);

#pragma unroll
    for (int pr = 0; pr < 4; pr++) {           // channel pairs (2c2, 2c2+1)
        float acc_e[4], acc_o[4];
#pragma unroll
        for (int half = 0; half < 2; half++) {
            int c = wid * 8 + pr * 2 + half;
            const float4* plane = xb + (size_t)c * 4096;
            float4 r0 = hasT ? plane[(h - 1) * 32 + lane] : z4;
            float4 r1 =        plane[h       * 32 + lane];
            float4 r2 = hasB ? plane[(h + 1) * 32 + lane] : z4;

            const float* wp = dws + c * 9;
            float a0 = 0.f, a1 = 0.f, a2 = 0.f, a3 = 0.f;
#pragma unroll
            for (int r = 0; r < 3; r++) {
                float4 m = (r == 0) ? r0 : (r == 1) ? r1 : r2;
                float lf = __shfl_up_sync(0xffffffffu, m.w, 1);
                float rg = __shfl_down_sync(0xffffffffu, m.x, 1);
                if (lane == 0)  lf = 0.f;
                if (lane == 31) rg = 0.f;
                float w0 = wp[r * 3 + 0], w1 = wp[r * 3 + 1], w2 = wp[r * 3 + 2];
                a0 += w0 * lf  + w1 * m.x + w2 * m.y;
                a1 += w0 * m.x + w1 * m.y + w2 * m.z;
                a2 += w0 * m.y + w1 * m.z + w2 * m.w;
                a3 += w0 * m.z + w1 * m.w + w2 * rg;
            }
            float* dst = half ? acc_o : acc_e;
            dst[0] = a0; dst[1] = a1; dst[2] = a2; dst[3] = a3;
        }
        // interleaved store: ys2[c2][w] float2 = (y_even[w], y_odd[w]); w = 4*lane..
        int c2 = wid * 4 + pr;
        float4* dst4 = (float4*)ys2 + c2 * 64 + 2 * lane;
        dst4[0] = make_float4(acc_e[0], acc_o[0], acc_e[1], acc_o[1]);
        dst4[1] = make_float4(acc_e[2], acc_o[2], acc_e[3], acc_o[3]);
    }
    __syncthreads();

    // ---- pointwise: c-pair split-K in f32x2; warp handles o [8w,8w+8), two w-halves ----
    const ulonglong2* pwv = (const ulonglong2*)pwT;   // pwv[c2*32 + o/2] = p(o), p(o+1)
    int ob = wid * 8;
    int pbase = ob >> 1;                               // u64-pair index within row
    float* outb = out + (size_t)(b * 64) * 16384 + (size_t)h * 128;

#pragma unroll 1
    for (int q = 0; q < 2; q++) {                // w-half: w = 64q + {2*lane, 2*lane+1}
        ull acc[16];
#pragma unroll
        for (int i = 0; i < 16; i++) acc[i] = 0ull;

        const ulonglong2* ybase = (const ulonglong2*)ys2 + 32 * q + lane;

#pragma unroll 8
        for (int c2 = 0; c2 < 32; c2++) {
            ulonglong2 yv = ybase[c2 * 64];      // (y2[c2][w0], y2[c2][w0+1])
            ull y0 = yv.x, y1 = yv.y;
#pragma unroll
            for (int j = 0; j < 4; j++) {        // 2 output channels per iteration
                ulonglong2 pp = pwv[c2 * 32 + pbase + j];
                asm("fma.rn.f32x2 %0, %1, %2, %0;" : "+l"(acc[4*j+0]) : "l"(y0), "l"(pp.x));
                asm("fma.rn.f32x2 %0, %1, %2, %0;" : "+l"(acc[4*j+1]) : "l"(y1), "l"(pp.x));
                asm("fma.rn.f32x2 %0, %1, %2, %0;" : "+l"(acc[4*j+2]) : "l"(y0), "l"(pp.y));
                asm("fma.rn.f32x2 %0, %1, %2, %0;" : "+l"(acc[4*j+3]) : "l"(y1), "l"(pp.y));
            }
        }

        // epilogue for this w-half: value = acc.x + acc.y + dbias
#pragma unroll
        for (int j = 0; j < 4; j++) {
#pragma unroll
            for (int s = 0; s < 2; s++) {
                int o = ob + 2 * j + s;
                float db = dbs[o];
                float a0x, a0y, a1x, a1y;
                asm("mov.b64 {%0,%1}, %2;" : "=f"(a0x), "=f"(a0y) : "l"(acc[4*j+2*s]));
                asm("mov.b64 {%0,%1}, %2;" : "=f"(a1x), "=f"(a1y) : "l"(acc[4*j+2*s+1]));
                float v0 = a0x + a0y + db;
                float v1 = a1x + a1y + db;

                *(float2*)(outb + (size_t)o * 16384 + 64 * q + 2 * lane) = make_float2(v0, v1);

                float ss  = v0 + v1;
                float ss2 = v0 * v0 + v1 * v1;
#pragma unroll
                for (int off = 16; off; off >>= 1) {
                    ss  += __shfl_down_sync(0xffffffffu, ss,  off);
                    ss2 += __shfl_down_sync(0xffffffffu, ss2, off);
                }
                if (lane == 0) {
                    atomicAdd(&sst[o],      ss);
                    atomicAdd(&sst[64 + o], ss2);
                }
            }
        }
    }

    __syncthreads();
    if (tid < 64)                 atomicAdd(&gSum[tid],         (double)sst[tid]);
    else if (tid < 128)           atomicAdd(&gSumSq[tid - 64],  (double)sst[tid]);
}

// =================================================================================
// Kernel 4: finalize BN scale/shift
// =================================================================================
__global__ void k_finalize(const float* __restrict__ gamma,
                           const float* __restrict__ beta)
{
    int t = threadIdx.x;
    if (t < 64) {
        const double n = 524288.0;   // 32 * 128 * 128
        double mean = gSum[t] / n;
        double var  = gSumSq[t] / n - mean * mean;
        double inv  = 1.0 / sqrt(var + 1e-5);
        double g    = (double)gamma[t];
        gScale[t] = (float)(g * inv);
        gShift[t] = (float)((double)beta[t] - mean * g * inv);
    }
}

// =================================================================================
// Kernel 5: apply BN in place (streaming, float4)
// =================================================================================
__global__ void __launch_bounds__(256) k_bn(float* __restrict__ out) {
    int i = blockIdx.x * 256 + threadIdx.x;      // float4 index
    float4 v = ((const float4*)out)[i];
    int o = (i >> 12) & 63;                      // 4096 float4 per (b,o) plane
    float sc = gScale[o], sh = gShift[o];
    v.x = fmaf(v.x, sc, sh);
    v.y = fmaf(v.y, sc, sh);
    v.z = fmaf(v.z, sc, sh);
    v.w = fmaf(v.w, sc, sh);
    ((float4*)out)[i] = v;
}

// =================================================================================
extern "C" void kernel_launch(void* const* d_in, const int* in_sizes, int n_in,
                              void* d_out, int out_size)
{
    const float* x      = (const float*)d_in[0];
    const float* cg_w1  = (const float*)d_in[1];
    const float* cg_b1  = (const float*)d_in[2];
    const float* cg_w2  = (const float*)d_in[3];
    const float* cg_b2  = (const float*)d_in[4];
    const float* wg_w   = (const float*)d_in[5];
    const float* wg_b   = (const float*)d_in[6];
    const float* pg_w   = (const float*)d_in[7];
    const float* pg_b   = (const float*)d_in[8];
    const float* bg_w   = (const float*)d_in[9];
    const float* bg_b   = (const float*)d_in[10];
    const float* bn_g   = (const float*)d_in[11];
    const float* bn_b   = (const float*)d_in[12];
    float* out = (float*)d_out;

    cudaFuncSetAttribute(k_main, cudaFuncAttributeMaxDynamicSharedMemorySize, 52224);

    k_zero<<<1, 64>>>();
    k_cond_sums<<<2048, 256>>>(x);
    k_gen<<<32, 256>>>(cg_w1, cg_b1, cg_w2, cg_b2, wg_w, wg_b, pg_w, pg_b, bg_w, bg_b);
    dim3 g3(128, 32);
    k_main<<<g3, 256, 52224>>>(x, out);
    k_finalize<<<1, 64>>>(bn_g, bn_b);
    k_bn<<<32768, 256>>>(out);
}

// round 5
// speedup vs baseline: 1.3964x; 1.3964x over previous
#include <cuda_runtime.h>
#include <cstdint>

typedef unsigned long long ull;

// ---------------- device scratch (no runtime allocation allowed) ----------------
__device__ float  gS[32 * 64 * 9];     // strided sums for cond conv
__device__ float  gDw[32 * 576];       // per-sample depthwise weights (fp32)
__device__ float  gPw[32 * 4096];      // per-sample pointwise weights [b][o][c], tf32-rounded
__device__ float  gDb[32 * 64];        // per-sample dynamic bias
__device__ double gSum[64], gSumSq[64];// BN statistics accumulators
__device__ float  gScale[64], gShift[64];

__device__ __forceinline__ float f2tf32(float x) {
    uint32_t u;
    asm("cvt.rna.tf32.f32 %0, %1;" : "=r"(u) : "f"(x));
    return __uint_as_float(u);
}

// =================================================================================
// Kernel 0: zero stats (graph replays must be deterministic)
// =================================================================================
__global__ void k_zero() {
    int t = threadIdx.x;
    if (t < 64) { gSum[t] = 0.0; gSumSq[t] = 0.0; }
}

// =================================================================================
// Kernel 1: per-(b,c) 9 strided sums S[kh][kw] = sum_{oh,ow} x[2oh+kh, 2ow+kw]
// =================================================================================
__global__ void __launch_bounds__(256) k_cond_sums(const float* __restrict__ x) {
    int bc = blockIdx.x;                 // b*64 + c
    int t  = threadIdx.x;
    const float* base = x + (size_t)bc * 16384;

    int i  = t >> 1;                     // row 0..127
    int j0 = (t & 1) * 64;               // half-row
    const float4* row4 = (const float4*)(base + i * 128 + j0);

    float ca0 = 0.f, ca1 = 0.f, ca2 = 0.f;
#pragma unroll
    for (int k = 0; k < 16; k++) {
        float4 v = row4[k];
        int j = j0 + 4 * k;
        ca0 += v.x + ((j <= 122) ? v.z : 0.f);
        ca1 += v.y + ((j <= 122) ? v.w : 0.f);
        ca2 += ((j >= 2) ? v.x : 0.f) + v.z;
    }
    bool ev = ((i & 1) == 0);
    float f0 = (ev  && i <= 124) ? 1.f : 0.f;
    float f1 = (!ev && i <= 125) ? 1.f : 0.f;
    float f2 = (ev  && i >= 2)   ? 1.f : 0.f;

    float bins[9] = { f0*ca0, f0*ca1, f0*ca2,
                      f1*ca0, f1*ca1, f1*ca2,
                      f2*ca0, f2*ca1, f2*ca2 };
#pragma unroll
    for (int off = 16; off; off >>= 1)
#pragma unroll
        for (int k = 0; k < 9; k++)
            bins[k] += __shfl_down_sync(0xffffffffu, bins[k], off);

    __shared__ float red[8][9];
    int lane = t & 31, w = t >> 5;
    if (lane == 0)
#pragma unroll
        for (int k = 0; k < 9; k++) red[w][k] = bins[k];
    __syncthreads();
    if (t < 9) {
        float s = 0.f;
#pragma unroll
        for (int ww = 0; ww < 8; ww++) s += red[ww][t];
        gS[bc * 9 + t] = s;
    }
}

// =================================================================================
// Kernel 2: per-sample condition vector + dynamic weight generation (tiny GEMMs)
// =================================================================================
__global__ void __launch_bounds__(256) k_gen(
    const float* __restrict__ cg_w1, const float* __restrict__ cg_b1,
    const float* __restrict__ cg_w2, const float* __restrict__ cg_b2,
    const float* __restrict__ wg_w,  const float* __restrict__ wg_b,
    const float* __restrict__ pg_w,  const float* __restrict__ pg_b,
    const float* __restrict__ bg_w,  const float* __restrict__ bg_b)
{
    __shared__ float Ss[576];
    __shared__ float parts[256];
    __shared__ float c0[16];
    __shared__ float cond[16];

    int b = blockIdx.x;
    int t = threadIdx.x;

    for (int idx = t; idx < 576; idx += 256) Ss[idx] = gS[b * 576 + idx];
    __syncthreads();

    {
        int co = t >> 4, part = t & 15;
        const float* wrow = cg_w1 + co * 576 + part * 36;
        const float* srow = Ss + part * 36;
        float s = 0.f;
#pragma unroll
        for (int k = 0; k < 36; k++) s += wrow[k] * srow[k];
        parts[t] = s;
    }
    __syncthreads();
    if (t < 16) {
        float s = 0.f;
#pragma unroll
        for (int p = 0; p < 16; p++) s += parts[t * 16 + p];
        s = s * (1.0f / 3969.0f) + cg_b1[t];
        c0[t] = fmaxf(s, 0.f);
    }
    __syncthreads();
    if (t < 16) {
        float s = cg_b2[t];
#pragma unroll
        for (int i = 0; i < 16; i++) s += c0[i] * cg_w2[t * 16 + i];
        cond[t] = fmaxf(s, 0.f);
    }
    __syncthreads();

    for (int r = t; r < 576; r += 256) {
        float s = wg_b[r];
        const float* wr = wg_w + r * 16;
#pragma unroll
        for (int q = 0; q < 16; q++) s += cond[q] * wr[q];
        gDw[b * 576 + r] = fmaxf(s, 0.f);
    }
    // pointwise weights [b][o][c], pre-rounded to tf32 for the MMA path
    for (int r = t; r < 4096; r += 256) {
        float s = pg_b[r];
        const float* wr = pg_w + r * 16;
#pragma unroll
        for (int q = 0; q < 16; q++) s += cond[q] * wr[q];
        gPw[b * 4096 + r] = f2tf32(fmaxf(s, 0.f));
    }
    if (t < 64) {
        float s = bg_b[t];
        const float* wr = bg_w + t * 16;
#pragma unroll
        for (int q = 0; q < 16; q++) s += cond[q] * wr[q];
        gDb[b * 64 + t] = s;
    }
}

// =================================================================================
// Kernel 3: fused depthwise3x3 (global->regs) + tf32 MMA pointwise (64x64 @ 128w)
//   one block per (h, b); 256 threads; 4 CTAs/SM.
// smem (floats):
//   ys  [64 c][136]   (128 w + 8 pad)  offset 0      (34816 B)
//   pwS [64 o][68]    (64 c + 4 pad)   offset 8704   (17408 B)
//   dws [576]                          offset 13056
//   dbs [64]                           offset 13632
//   sst [128] (s[64], s2[64])          offset 13696  -> 13824 fl = 55296 B
// MMA: D[64 o][128 w] = A(pw[64][64], row-major K) x B(y[64][128], col-major K)
//   warp = (m-tile = wid>>1 -> o base 16*(wid>>1), n-half = wid&1 -> w base 64*(wid&1))
//   per warp: 8 k-steps x 8 n-tiles of m16n8k8.
// =================================================================================
__global__ void __launch_bounds__(256, 4) k_main(const float* __restrict__ x,
                                                 float* __restrict__ out)
{
    extern __shared__ float sm[];
    float* ys  = sm;
    float* pwS = sm + 8704;
    float* dws = sm + 13056;
    float* dbs = sm + 13632;
    float* sst = sm + 13696;

    int tid  = threadIdx.x;
    int lane = tid & 31, wid = tid >> 5;
    int h = blockIdx.x, b = blockIdx.y;

    // ---- stage per-sample dynamic weights into smem ----
    {
        const float* pwg = gPw + b * 4096;
#pragma unroll
        for (int k = 0; k < 16; k++) {
            int idx = tid + 256 * k;
            int o = idx >> 6, c = idx & 63;
            pwS[o * 68 + c] = pwg[idx];
        }
        for (int idx = tid; idx < 576; idx += 256) dws[idx] = gDw[b * 576 + idx];
        if (tid < 64) dbs[tid] = gDb[b * 64 + tid];
        if (tid < 128) sst[tid] = 0.f;
    }
    __syncthreads();

    // ---- depthwise 3x3 (pad=1) straight from global; warp w: channels [8w,8w+8) ----
    const float4* xb = (const float4*)(x + (size_t)b * 64 * 16384);
    const float4 z4 = make_float4(0.f, 0.f, 0.f, 0.f);
    bool hasT = (h >= 1), hasB = (h <= 126);

#pragma unroll
    for (int ci = 0; ci < 8; ci++) {
        int c = wid * 8 + ci;
        const float4* plane = xb + (size_t)c * 4096;
        float4 r0 = hasT ? plane[(h - 1) * 32 + lane] : z4;
        float4 r1 =        plane[h       * 32 + lane];
        float4 r2 = hasB ? plane[(h + 1) * 32 + lane] : z4;

        const float* wp = dws + c * 9;
        float a0 = 0.f, a1 = 0.f, a2 = 0.f, a3 = 0.f;
#pragma unroll
        for (int r = 0; r < 3; r++) {
            float4 m = (r == 0) ? r0 : (r == 1) ? r1 : r2;
            float lf = __shfl_up_sync(0xffffffffu, m.w, 1);
            float rg = __shfl_down_sync(0xffffffffu, m.x, 1);
            if (lane == 0)  lf = 0.f;
            if (lane == 31) rg = 0.f;
            float w0 = wp[r * 3 + 0], w1 = wp[r * 3 + 1], w2 = wp[r * 3 + 2];
            a0 += w0 * lf  + w1 * m.x + w2 * m.y;
            a1 += w0 * m.x + w1 * m.y + w2 * m.z;
            a2 += w0 * m.y + w1 * m.z + w2 * m.w;
            a3 += w0 * m.z + w1 * m.w + w2 * rg;
        }
        // pre-round to tf32 and store row-major [c][w] (pad 136)
        *(float4*)(ys + c * 136 + 4 * lane) =
            make_float4(f2tf32(a0), f2tf32(a1), f2tf32(a2), f2tf32(a3));
    }
    __syncthreads();

    // ---- tf32 MMA pointwise ----
    int mt = wid >> 1, nh = wid & 1;
    int ob = mt * 16;
    int g = lane >> 2, t4 = lane & 3;

    float db0 = dbs[ob + g];
    float db1 = dbs[ob + g + 8];

    float acc[8][4];
#pragma unroll
    for (int n = 0; n < 8; n++) {
        acc[n][0] = 0.f; acc[n][1] = 0.f; acc[n][2] = 0.f; acc[n][3] = 0.f;
    }

#pragma unroll
    for (int k = 0; k < 8; k++) {
        int k0 = 8 * k;
        const float* aR0 = pwS + (ob + g) * 68 + k0 + t4;
        uint32_t a0 = __float_as_uint(aR0[0]);
        uint32_t a2 = __float_as_uint(aR0[4]);
        uint32_t a1 = __float_as_uint(aR0[8 * 68]);
        uint32_t a3 = __float_as_uint(aR0[8 * 68 + 4]);

        const float* bR0 = ys + (k0 + t4) * 136 + 64 * nh + g;
#pragma unroll
        for (int n = 0; n < 8; n++) {
            uint32_t b0 = __float_as_uint(bR0[8 * n]);
            uint32_t b1 = __float_as_uint(bR0[4 * 136 + 8 * n]);
            asm("mma.sync.aligned.m16n8k8.row.col.f32.tf32.tf32.f32 "
                "{%0,%1,%2,%3}, {%4,%5,%6,%7}, {%8,%9}, {%0,%1,%2,%3};"
                : "+f"(acc[n][0]), "+f"(acc[n][1]), "+f"(acc[n][2]), "+f"(acc[n][3])
                : "r"(a0), "r"(a1), "r"(a2), "r"(a3), "r"(b0), "r"(b1));
        }
    }

    // ---- epilogue: +dbias, store, BN partial stats ----
    float* outb = out + (size_t)(b * 64) * 16384 + (size_t)h * 128;
    float sl = 0.f, s2l = 0.f, sh = 0.f, s2h = 0.f;
    size_t oLo = (size_t)(ob + g) * 16384;
    size_t oHi = (size_t)(ob + g + 8) * 16384;

#pragma unroll
    for (int n = 0; n < 8; n++) {
        int w = 64 * nh + 8 * n + 2 * t4;
        float v0 = acc[n][0] + db0;
        float v1 = acc[n][1] + db0;
        float v2 = acc[n][2] + db1;
        float v3 = acc[n][3] + db1;
        *(float2*)(outb + oLo + w) = make_float2(v0, v1);
        *(float2*)(outb + oHi + w) = make_float2(v2, v3);
        sl  += v0 + v1;      s2l += v0 * v0 + v1 * v1;
        sh  += v2 + v3;      s2h += v2 * v2 + v3 * v3;
    }
#pragma unroll
    for (int off = 1; off <= 2; off <<= 1) {
        sl  += __shfl_xor_sync(0xffffffffu, sl,  off);
        s2l += __shfl_xor_sync(0xffffffffu, s2l, off);
        sh  += __shfl_xor_sync(0xffffffffu, sh,  off);
        s2h += __shfl_xor_sync(0xffffffffu, s2h, off);
    }
    if (t4 == 0) {
        atomicAdd(&sst[ob + g],          sl);
        atomicAdd(&sst[64 + ob + g],     s2l);
        atomicAdd(&sst[ob + g + 8],      sh);
        atomicAdd(&sst[64 + ob + g + 8], s2h);
    }

    __syncthreads();
    if (tid < 64)       atomicAdd(&gSum[tid],        (double)sst[tid]);
    else if (tid < 128) atomicAdd(&gSumSq[tid - 64], (double)sst[tid]);
}

// =================================================================================
// Kernel 4: finalize BN scale/shift
// =================================================================================
__global__ void k_finalize(const float* __restrict__ gamma,
                           const float* __restrict__ beta)
{
    int t = threadIdx.x;
    if (t < 64) {
        const double n = 524288.0;   // 32 * 128 * 128
        double mean = gSum[t] / n;
        double var  = gSumSq[t] / n - mean * mean;
        double inv  = 1.0 / sqrt(var + 1e-5);
        double g    = (double)gamma[t];
        gScale[t] = (float)(g * inv);
        gShift[t] = (float)((double)beta[t] - mean * g * inv);
    }
}

// =================================================================================
// Kernel 5: apply BN in place (streaming, float4)
// =================================================================================
__global__ void __launch_bounds__(256) k_bn(float* __restrict__ out) {
    int i = blockIdx.x * 256 + threadIdx.x;      // float4 index
    float4 v = ((const float4*)out)[i];
    int o = (i >> 12) & 63;                      // 4096 float4 per (b,o) plane
    float sc = gScale[o], sh = gShift[o];
    v.x = fmaf(v.x, sc, sh);
    v.y = fmaf(v.y, sc, sh);
    v.z = fmaf(v.z, sc, sh);
    v.w = fmaf(v.w, sc, sh);
    ((float4*)out)[i] = v;
}

// =================================================================================
extern "C" void kernel_launch(void* const* d_in, const int* in_sizes, int n_in,
                              void* d_out, int out_size)
{
    const float* x      = (const float*)d_in[0];
    const float* cg_w1  = (const float*)d_in[1];
    const float* cg_b1  = (const float*)d_in[2];
    const float* cg_w2  = (const float*)d_in[3];
    const float* cg_b2  = (const float*)d_in[4];
    const float* wg_w   = (const float*)d_in[5];
    const float* wg_b   = (const float*)d_in[6];
    const float* pg_w   = (const float*)d_in[7];
    const float* pg_b   = (const float*)d_in[8];
    const float* bg_w   = (const float*)d_in[9];
    const float* bg_b   = (const float*)d_in[10];
    const float* bn_g   = (const float*)d_in[11];
    const float* bn_b   = (const float*)d_in[12];
    float* out = (float*)d_out;

    cudaFuncSetAttribute(k_main, cudaFuncAttributeMaxDynamicSharedMemorySize, 55296);

    k_zero<<<1, 64>>>();
    k_cond_sums<<<2048, 256>>>(x);
    k_gen<<<32, 256>>>(cg_w1, cg_b1, cg_w2, cg_b2, wg_w, wg_b, pg_w, pg_b, bg_w, bg_b);
    dim3 g3(128, 32);
    k_main<<<g3, 256, 55296>>>(x, out);
    k_finalize<<<1, 64>>>(bn_g, bn_b);
    k_bn<<<32768, 256>>>(out);
}

// round 6
// speedup vs baseline: 1.4057x; 1.0067x over previous
#include <cuda_runtime.h>
#include <cstdint>

typedef unsigned long long ull;

// ---------------- device scratch (no runtime allocation allowed) ----------------
__device__ float  gS[32 * 64 * 9];     // strided sums for cond conv
__device__ float  gDw[32 * 576];       // per-sample depthwise weights (fp32)
__device__ float  gPw[32 * 4096];      // per-sample pointwise weights [b][o][c], tf32-rounded
__device__ float  gDb[32 * 64];        // per-sample dynamic bias
__device__ double gSum[64], gSumSq[64];// BN statistics accumulators
__device__ float  gScale[64], gShift[64];

__device__ __forceinline__ float f2tf32(float x) {
    uint32_t u;
    asm("cvt.rna.tf32.f32 %0, %1;" : "=r"(u) : "f"(x));
    return __uint_as_float(u);
}

// =================================================================================
// Kernel 0: zero stats (graph replays must be deterministic)
// =================================================================================
__global__ void k_zero() {
    int t = threadIdx.x;
    if (t < 64) { gSum[t] = 0.0; gSumSq[t] = 0.0; }
}

// =================================================================================
// Kernel 1: per-(b,c) 9 strided sums S[kh][kw] = sum_{oh,ow} x[2oh+kh, 2ow+kw]
// =================================================================================
__global__ void __launch_bounds__(256) k_cond_sums(const float* __restrict__ x) {
    int bc = blockIdx.x;                 // b*64 + c
    int t  = threadIdx.x;
    const float* base = x + (size_t)bc * 16384;

    int i  = t >> 1;                     // row 0..127
    int j0 = (t & 1) * 64;               // half-row
    const float4* row4 = (const float4*)(base + i * 128 + j0);

    float ca0 = 0.f, ca1 = 0.f, ca2 = 0.f;
#pragma unroll
    for (int k = 0; k < 16; k++) {
        float4 v = row4[k];
        int j = j0 + 4 * k;
        ca0 += v.x + ((j <= 122) ? v.z : 0.f);
        ca1 += v.y + ((j <= 122) ? v.w : 0.f);
        ca2 += ((j >= 2) ? v.x : 0.f) + v.z;
    }
    bool ev = ((i & 1) == 0);
    float f0 = (ev  && i <= 124) ? 1.f : 0.f;
    float f1 = (!ev && i <= 125) ? 1.f : 0.f;
    float f2 = (ev  && i >= 2)   ? 1.f : 0.f;

    float bins[9] = { f0*ca0, f0*ca1, f0*ca2,
                      f1*ca0, f1*ca1, f1*ca2,
                      f2*ca0, f2*ca1, f2*ca2 };
#pragma unroll
    for (int off = 16; off; off >>= 1)
#pragma unroll
        for (int k = 0; k < 9; k++)
            bins[k] += __shfl_down_sync(0xffffffffu, bins[k], off);

    __shared__ float red[8][9];
    int lane = t & 31, w = t >> 5;
    if (lane == 0)
#pragma unroll
        for (int k = 0; k < 9; k++) red[w][k] = bins[k];
    __syncthreads();
    if (t < 9) {
        float s = 0.f;
#pragma unroll
        for (int ww = 0; ww < 8; ww++) s += red[ww][t];
        gS[bc * 9 + t] = s;
    }
}

// =================================================================================
// Kernel 2: per-sample condition vector + dynamic weight generation (tiny GEMMs)
// =================================================================================
__global__ void __launch_bounds__(256) k_gen(
    const float* __restrict__ cg_w1, const float* __restrict__ cg_b1,
    const float* __restrict__ cg_w2, const float* __restrict__ cg_b2,
    const float* __restrict__ wg_w,  const float* __restrict__ wg_b,
    const float* __restrict__ pg_w,  const float* __restrict__ pg_b,
    const float* __restrict__ bg_w,  const float* __restrict__ bg_b)
{
    __shared__ float Ss[576];
    __shared__ float parts[256];
    __shared__ float c0[16];
    __shared__ float cond[16];

    int b = blockIdx.x;
    int t = threadIdx.x;

    for (int idx = t; idx < 576; idx += 256) Ss[idx] = gS[b * 576 + idx];
    __syncthreads();

    {
        int co = t >> 4, part = t & 15;
        const float* wrow = cg_w1 + co * 576 + part * 36;
        const float* srow = Ss + part * 36;
        float s = 0.f;
#pragma unroll
        for (int k = 0; k < 36; k++) s += wrow[k] * srow[k];
        parts[t] = s;
    }
    __syncthreads();
    if (t < 16) {
        float s = 0.f;
#pragma unroll
        for (int p = 0; p < 16; p++) s += parts[t * 16 + p];
        s = s * (1.0f / 3969.0f) + cg_b1[t];
        c0[t] = fmaxf(s, 0.f);
    }
    __syncthreads();
    if (t < 16) {
        float s = cg_b2[t];
#pragma unroll
        for (int i = 0; i < 16; i++) s += c0[i] * cg_w2[t * 16 + i];
        cond[t] = fmaxf(s, 0.f);
    }
    __syncthreads();

    for (int r = t; r < 576; r += 256) {
        float s = wg_b[r];
        const float* wr = wg_w + r * 16;
#pragma unroll
        for (int q = 0; q < 16; q++) s += cond[q] * wr[q];
        gDw[b * 576 + r] = fmaxf(s, 0.f);
    }
    // pointwise weights [b][o][c], pre-rounded to tf32 for the MMA path
    for (int r = t; r < 4096; r += 256) {
        float s = pg_b[r];
        const float* wr = pg_w + r * 16;
#pragma unroll
        for (int q = 0; q < 16; q++) s += cond[q] * wr[q];
        gPw[b * 4096 + r] = f2tf32(fmaxf(s, 0.f));
    }
    if (t < 64) {
        float s = bg_b[t];
        const float* wr = bg_w + t * 16;
#pragma unroll
        for (int q = 0; q < 16; q++) s += cond[q] * wr[q];
        gDb[b * 64 + t] = s;
    }
}

// =================================================================================
// Kernel 3: fused depthwise3x3 (global->regs) + tf32 MMA pointwise (64x64 @ 128w)
//   one block per (h, b); 256 threads; 4 CTAs/SM.
// smem (floats):
//   ys  [64 c][136]   (128 w + 8 pad)  offset 0       (8704 fl)
//   pwS [64 o][68]    (64 c + 4 pad)   offset 8704    (4352 fl)
//   dws [64 c][12]    (9 + 3 pad)      offset 13056   (768 fl)
//   dbs [64]                           offset 13824
//   sst [128] (s[64], s2[64])          offset 13888   -> 14016 fl = 56064 B
// MMA: D[64 o][128 w] = A(pw[64][64], row K) x B(y[64][128], col K)
//   warp tile M32 x N32:  mt = wid>>2 (o base 32mt), nb = wid&3 (w base 32nb)
//   per warp: 8 k-steps x {2 m-subtiles x 4 n-subtiles} of m16n8k8; B frag reused 2x.
// =================================================================================
__global__ void __launch_bounds__(256, 4) k_main(const float* __restrict__ x,
                                                 float* __restrict__ out)
{
    extern __shared__ float sm[];
    float* ys  = sm;
    float* pwS = sm + 8704;
    float* dws = sm + 13056;
    float* dbs = sm + 13824;
    float* sst = sm + 13888;

    int tid  = threadIdx.x;
    int lane = tid & 31, wid = tid >> 5;
    int h = blockIdx.x, b = blockIdx.y;

    // ---- stage per-sample dynamic weights into smem ----
    {
        const float* pwg = gPw + b * 4096;
#pragma unroll
        for (int k = 0; k < 16; k++) {
            int idx = tid + 256 * k;
            int o = idx >> 6, c = idx & 63;
            pwS[o * 68 + c] = pwg[idx];
        }
        for (int idx = tid; idx < 576; idx += 256) {
            int c = idx / 9, j = idx - 9 * c;
            dws[c * 12 + j] = gDw[b * 576 + idx];
        }
        if (tid < 64) dbs[tid] = gDb[b * 64 + tid];
        if (tid < 128) sst[tid] = 0.f;
    }
    __syncthreads();

    // ---- depthwise 3x3 (pad=1) straight from global; warp w: channels [8w,8w+8) ----
    const float4* xb = (const float4*)(x + (size_t)b * 64 * 16384);
    const float4 z4 = make_float4(0.f, 0.f, 0.f, 0.f);
    bool hasT = (h >= 1), hasB = (h <= 126);

#pragma unroll
    for (int ci = 0; ci < 8; ci++) {
        int c = wid * 8 + ci;
        const float4* plane = xb + (size_t)c * 4096;
        float4 r0 = hasT ? plane[(h - 1) * 32 + lane] : z4;
        float4 r1 =        plane[h       * 32 + lane];
        float4 r2 = hasB ? plane[(h + 1) * 32 + lane] : z4;

        const float* wp = dws + c * 12;
        float4 wA = *(const float4*)(wp);       // w00 w01 w02 w10
        float4 wB = *(const float4*)(wp + 4);   // w11 w12 w20 w21
        float  w8 = wp[8];                      // w22

        float a0 = 0.f, a1 = 0.f, a2 = 0.f, a3 = 0.f;
#pragma unroll
        for (int r = 0; r < 3; r++) {
            float4 m = (r == 0) ? r0 : (r == 1) ? r1 : r2;
            float lf = __shfl_up_sync(0xffffffffu, m.w, 1);
            float rg = __shfl_down_sync(0xffffffffu, m.x, 1);
            if (lane == 0)  lf = 0.f;
            if (lane == 31) rg = 0.f;
            float w0 = (r == 0) ? wA.x : (r == 1) ? wA.w : wB.z;
            float w1 = (r == 0) ? wA.y : (r == 1) ? wB.x : wB.w;
            float w2 = (r == 0) ? wA.z : (r == 1) ? wB.y : w8;
            a0 += w0 * lf  + w1 * m.x + w2 * m.y;
            a1 += w0 * m.x + w1 * m.y + w2 * m.z;
            a2 += w0 * m.y + w1 * m.z + w2 * m.w;
            a3 += w0 * m.z + w1 * m.w + w2 * rg;
        }
        *(float4*)(ys + c * 136 + 4 * lane) =
            make_float4(f2tf32(a0), f2tf32(a1), f2tf32(a2), f2tf32(a3));
    }
    __syncthreads();

    // ---- tf32 MMA pointwise, warp tile M32 x N32 ----
    int mt = wid >> 2, nb = wid & 3;
    int ob = mt * 32, wbase = nb * 32;
    int g = lane >> 2, t4 = lane & 3;

    float acc[2][4][4];
#pragma unroll
    for (int ms = 0; ms < 2; ms++)
#pragma unroll
        for (int n = 0; n < 4; n++)
#pragma unroll
            for (int j = 0; j < 4; j++) acc[ms][n][j] = 0.f;

#pragma unroll 2
    for (int k = 0; k < 8; k++) {
        int k0 = 8 * k;
        uint32_t a[2][4];
#pragma unroll
        for (int ms = 0; ms < 2; ms++) {
            const float* aR = pwS + (ob + 16 * ms + g) * 68 + k0 + t4;
            a[ms][0] = __float_as_uint(aR[0]);
            a[ms][2] = __float_as_uint(aR[4]);
            a[ms][1] = __float_as_uint(aR[8 * 68]);
            a[ms][3] = __float_as_uint(aR[8 * 68 + 4]);
        }
        const float* bR = ys + (k0 + t4) * 136 + wbase + g;
#pragma unroll
        for (int n = 0; n < 4; n++) {
            uint32_t b0 = __float_as_uint(bR[8 * n]);
            uint32_t b1 = __float_as_uint(bR[4 * 136 + 8 * n]);
#pragma unroll
            for (int ms = 0; ms < 2; ms++) {
                asm("mma.sync.aligned.m16n8k8.row.col.f32.tf32.tf32.f32 "
                    "{%0,%1,%2,%3}, {%4,%5,%6,%7}, {%8,%9}, {%0,%1,%2,%3};"
                    : "+f"(acc[ms][n][0]), "+f"(acc[ms][n][1]),
                      "+f"(acc[ms][n][2]), "+f"(acc[ms][n][3])
                    : "r"(a[ms][0]), "r"(a[ms][1]), "r"(a[ms][2]), "r"(a[ms][3]),
                      "r"(b0), "r"(b1));
            }
        }
    }

    // ---- epilogue: +dbias, store, BN partial stats ----
    float* outb = out + (size_t)(b * 64) * 16384 + (size_t)h * 128;
    float sAcc[2][2], s2Acc[2][2];
#pragma unroll
    for (int ms = 0; ms < 2; ms++) {
        sAcc[ms][0] = 0.f; sAcc[ms][1] = 0.f;
        s2Acc[ms][0] = 0.f; s2Acc[ms][1] = 0.f;
    }

#pragma unroll
    for (int ms = 0; ms < 2; ms++) {
        int rLo = ob + 16 * ms + g;
        float dbLo = dbs[rLo], dbHi = dbs[rLo + 8];
        size_t oLo = (size_t)rLo * 16384;
        size_t oHi = (size_t)(rLo + 8) * 16384;
#pragma unroll
        for (int n = 0; n < 4; n++) {
            int w = wbase + 8 * n + 2 * t4;
            float v0 = acc[ms][n][0] + dbLo;
            float v1 = acc[ms][n][1] + dbLo;
            float v2 = acc[ms][n][2] + dbHi;
            float v3 = acc[ms][n][3] + dbHi;
            *(float2*)(outb + oLo + w) = make_float2(v0, v1);
            *(float2*)(outb + oHi + w) = make_float2(v2, v3);
            sAcc[ms][0]  += v0 + v1;            s2Acc[ms][0] += v0 * v0 + v1 * v1;
            sAcc[ms][1]  += v2 + v3;            s2Acc[ms][1] += v2 * v2 + v3 * v3;
        }
    }
#pragma unroll
    for (int off = 1; off <= 2; off <<= 1)
#pragma unroll
        for (int ms = 0; ms < 2; ms++)
#pragma unroll
            for (int hl = 0; hl < 2; hl++) {
                sAcc[ms][hl]  += __shfl_xor_sync(0xffffffffu, sAcc[ms][hl],  off);
                s2Acc[ms][hl] += __shfl_xor_sync(0xffffffffu, s2Acc[ms][hl], off);
            }
    if (t4 == 0) {
#pragma unroll
        for (int ms = 0; ms < 2; ms++)
#pragma unroll
            for (int hl = 0; hl < 2; hl++) {
                int o = ob + 16 * ms + 8 * hl + g;
                atomicAdd(&sst[o],      sAcc[ms][hl]);
                atomicAdd(&sst[64 + o], s2Acc[ms][hl]);
            }
    }

    __syncthreads();
    if (tid < 64)       atomicAdd(&gSum[tid],        (double)sst[tid]);
    else if (tid < 128) atomicAdd(&gSumSq[tid - 64], (double)sst[tid]);
}

// =================================================================================
// Kernel 4: finalize BN scale/shift
// =================================================================================
__global__ void k_finalize(const float* __restrict__ gamma,
                           const float* __restrict__ beta)
{
    int t = threadIdx.x;
    if (t < 64) {
        const double n = 524288.0;   // 32 * 128 * 128
        double mean = gSum[t] / n;
        double var  = gSumSq[t] / n - mean * mean;
        double inv  = 1.0 / sqrt(var + 1e-5);
        double g    = (double)gamma[t];
        gScale[t] = (float)(g * inv);
        gShift[t] = (float)((double)beta[t] - mean * g * inv);
    }
}

// =================================================================================
// Kernel 5: apply BN in place (streaming, float4, MLP=4)
// =================================================================================
__global__ void __launch_bounds__(256) k_bn(float* __restrict__ out) {
    int base = blockIdx.x * 1024 + threadIdx.x;
    float4 v[4];
    int idx[4];
#pragma unroll
    for (int j = 0; j < 4; j++) {
        idx[j] = base + 256 * j;
        v[j] = ((const float4*)out)[idx[j]];
    }
#pragma unroll
    for (int j = 0; j < 4; j++) {
        int o = (idx[j] >> 12) & 63;             // 4096 float4 per (b,o) plane
        float sc = gScale[o], sh = gShift[o];
        v[j].x = fmaf(v[j].x, sc, sh);
        v[j].y = fmaf(v[j].y, sc, sh);
        v[j].z = fmaf(v[j].z, sc, sh);
        v[j].w = fmaf(v[j].w, sc, sh);
        ((float4*)out)[idx[j]] = v[j];
    }
}

// =================================================================================
extern "C" void kernel_launch(void* const* d_in, const int* in_sizes, int n_in,
                              void* d_out, int out_size)
{
    const float* x      = (const float*)d_in[0];
    const float* cg_w1  = (const float*)d_in[1];
    const float* cg_b1  = (const float*)d_in[2];
    const float* cg_w2  = (const float*)d_in[3];
    const float* cg_b2  = (const float*)d_in[4];
    const float* wg_w   = (const float*)d_in[5];
    const float* wg_b   = (const float*)d_in[6];
    const float* pg_w   = (const float*)d_in[7];
    const float* pg_b   = (const float*)d_in[8];
    const float* bg_w   = (const float*)d_in[9];
    const float* bg_b   = (const float*)d_in[10];
    const float* bn_g   = (const float*)d_in[11];
    const float* bn_b   = (const float*)d_in[12];
    float* out = (float*)d_out;

    cudaFuncSetAttribute(k_main, cudaFuncAttributeMaxDynamicSharedMemorySize, 56064);

    k_zero<<<1, 64>>>();
    k_cond_sums<<<2048, 256>>>(x);
    k_gen<<<32, 256>>>(cg_w1, cg_b1, cg_w2, cg_b2, wg_w, wg_b, pg_w, pg_b, bg_w, bg_b);
    dim3 g3(128, 32);
    k_main<<<g3, 256, 56064>>>(x, out);
    k_finalize<<<1, 64>>>(bn_g, bn_b);
    k_bn<<<8192, 256>>>(out);
}

// round 7
// speedup vs baseline: 1.5123x; 1.0758x over previous
#include <cuda_runtime.h>
#include <cstdint>

typedef unsigned long long ull;

// ---------------- device scratch (no runtime allocation allowed) ----------------
__device__ float  gS[32 * 64 * 9];     // strided sums for cond conv
__device__ float  gDw[32 * 576];       // per-sample depthwise weights (fp32)
__device__ float  gPw[32 * 4096];      // per-sample pointwise weights [b][o][c], tf32-rounded
__device__ float  gDb[32 * 64];        // per-sample dynamic bias
__device__ double gSum[64], gSumSq[64];// BN statistics accumulators
__device__ float  gScale[64], gShift[64];

__device__ __forceinline__ float f2tf32(float x) {
    uint32_t u;
    asm("cvt.rna.tf32.f32 %0, %1;" : "=r"(u) : "f"(x));
    return __uint_as_float(u);
}

// =================================================================================
// Kernel 0: zero stats (graph replays must be deterministic)
// =================================================================================
__global__ void k_zero() {
    int t = threadIdx.x;
    if (t < 64) { gSum[t] = 0.0; gSumSq[t] = 0.0; }
}

// =================================================================================
// Kernel 1: per-(b,c) 9 strided sums S[kh][kw] = sum_{oh,ow} x[2oh+kh, 2ow+kw]
// =================================================================================
__global__ void __launch_bounds__(256) k_cond_sums(const float* __restrict__ x) {
    int bc = blockIdx.x;                 // b*64 + c
    int t  = threadIdx.x;
    const float* base = x + (size_t)bc * 16384;

    int i  = t >> 1;                     // row 0..127
    int j0 = (t & 1) * 64;               // half-row
    const float4* row4 = (const float4*)(base + i * 128 + j0);

    float ca0 = 0.f, ca1 = 0.f, ca2 = 0.f;
#pragma unroll
    for (int k = 0; k < 16; k++) {
        float4 v = row4[k];
        int j = j0 + 4 * k;
        ca0 += v.x + ((j <= 122) ? v.z : 0.f);
        ca1 += v.y + ((j <= 122) ? v.w : 0.f);
        ca2 += ((j >= 2) ? v.x : 0.f) + v.z;
    }
    bool ev = ((i & 1) == 0);
    float f0 = (ev  && i <= 124) ? 1.f : 0.f;
    float f1 = (!ev && i <= 125) ? 1.f : 0.f;
    float f2 = (ev  && i >= 2)   ? 1.f : 0.f;

    float bins[9] = { f0*ca0, f0*ca1, f0*ca2,
                      f1*ca0, f1*ca1, f1*ca2,
                      f2*ca0, f2*ca1, f2*ca2 };
#pragma unroll
    for (int off = 16; off; off >>= 1)
#pragma unroll
        for (int k = 0; k < 9; k++)
            bins[k] += __shfl_down_sync(0xffffffffu, bins[k], off);

    __shared__ float red[8][9];
    int lane = t & 31, w = t >> 5;
    if (lane == 0)
#pragma unroll
        for (int k = 0; k < 9; k++) red[w][k] = bins[k];
    __syncthreads();
    if (t < 9) {
        float s = 0.f;
#pragma unroll
        for (int ww = 0; ww < 8; ww++) s += red[ww][t];
        gS[bc * 9 + t] = s;
    }
}

// =================================================================================
// Kernel 2: per-sample condition vector + dynamic weight generation (tiny GEMMs)
// =================================================================================
__global__ void __launch_bounds__(256) k_gen(
    const float* __restrict__ cg_w1, const float* __restrict__ cg_b1,
    const float* __restrict__ cg_w2, const float* __restrict__ cg_b2,
    const float* __restrict__ wg_w,  const float* __restrict__ wg_b,
    const float* __restrict__ pg_w,  const float* __restrict__ pg_b,
    const float* __restrict__ bg_w,  const float* __restrict__ bg_b)
{
    __shared__ float Ss[576];
    __shared__ float parts[256];
    __shared__ float c0[16];
    __shared__ float cond[16];

    int b = blockIdx.x;
    int t = threadIdx.x;

    for (int idx = t; idx < 576; idx += 256) Ss[idx] = gS[b * 576 + idx];
    __syncthreads();

    {
        int co = t >> 4, part = t & 15;
        const float* wrow = cg_w1 + co * 576 + part * 36;
        const float* srow = Ss + part * 36;
        float s = 0.f;
#pragma unroll
        for (int k = 0; k < 36; k++) s += wrow[k] * srow[k];
        parts[t] = s;
    }
    __syncthreads();
    if (t < 16) {
        float s = 0.f;
#pragma unroll
        for (int p = 0; p < 16; p++) s += parts[t * 16 + p];
        s = s * (1.0f / 3969.0f) + cg_b1[t];
        c0[t] = fmaxf(s, 0.f);
    }
    __syncthreads();
    if (t < 16) {
        float s = cg_b2[t];
#pragma unroll
        for (int i = 0; i < 16; i++) s += c0[i] * cg_w2[t * 16 + i];
        cond[t] = fmaxf(s, 0.f);
    }
    __syncthreads();

    for (int r = t; r < 576; r += 256) {
        float s = wg_b[r];
        const float* wr = wg_w + r * 16;
#pragma unroll
        for (int q = 0; q < 16; q++) s += cond[q] * wr[q];
        gDw[b * 576 + r] = fmaxf(s, 0.f);
    }
    // pointwise weights [b][o][c], pre-rounded to tf32 for the MMA path
    for (int r = t; r < 4096; r += 256) {
        float s = pg_b[r];
        const float* wr = pg_w + r * 16;
#pragma unroll
        for (int q = 0; q < 16; q++) s += cond[q] * wr[q];
        gPw[b * 4096 + r] = f2tf32(fmaxf(s, 0.f));
    }
    if (t < 64) {
        float s = bg_b[t];
        const float* wr = bg_w + t * 16;
#pragma unroll
        for (int q = 0; q < 16; q++) s += cond[q] * wr[q];
        gDb[b * 64 + t] = s;
    }
}

// =================================================================================
// Kernel 3: fused depthwise3x3 + tf32 MMA pointwise, HS=2 output rows per CTA.
//   512 threads; 2 CTAs/SM; grid (64, 32).
// smem (floats):
//   ys  [2 row][64 c][136]  offset 0       (17408 fl)
//   pwS [64 o][68]          offset 17408   (4352 fl)
//   dws [64 c][12]          offset 21760   (768 fl)
//   dbs [64]                offset 22528
//   sst [128]               offset 22592   -> 22720 fl = 90880 B
// Depthwise: warp w handles channels [4w, 4w+4); loads 4 x-rows/channel,
//   computes 2 output rows, shuffles hoisted across rows.
// MMA: warp -> (row = wid>>3, mt = (wid>>2)&1, nb = wid&3); M32 x N32 per warp.
// =================================================================================
__global__ void __launch_bounds__(512, 2) k_main(const float* __restrict__ x,
                                                 float* __restrict__ out)
{
    extern __shared__ float sm[];
    float* ys  = sm;
    float* pwS = sm + 17408;
    float* dws = sm + 21760;
    float* dbs = sm + 22528;
    float* sst = sm + 22592;

    int tid  = threadIdx.x;
    int lane = tid & 31, wid = tid >> 5;
    int h0 = blockIdx.x * 2, b = blockIdx.y;

    // ---- stage per-sample dynamic weights into smem ----
    {
        const float* pwg = gPw + b * 4096;
#pragma unroll
        for (int k = 0; k < 8; k++) {
            int idx = tid + 512 * k;
            int o = idx >> 6, c = idx & 63;
            pwS[o * 68 + c] = pwg[idx];
        }
        for (int idx = tid; idx < 576; idx += 512) {
            int c = idx / 9, j = idx - 9 * c;
            dws[c * 12 + j] = gDw[b * 576 + idx];
        }
        if (tid < 64) dbs[tid] = gDb[b * 64 + tid];
        else if (tid >= 64 && tid < 192) sst[tid - 64] = 0.f;
    }
    __syncthreads();

    // ---- depthwise 3x3 (pad=1); warp w: channels [4w, 4w+4); 2 output rows ----
    const float4* xb = (const float4*)(x + (size_t)b * 64 * 16384);
    const float4 z4 = make_float4(0.f, 0.f, 0.f, 0.f);
    bool hasT = (h0 >= 1), hasB = (h0 <= 125);

#pragma unroll
    for (int ci = 0; ci < 4; ci++) {
        int c = wid * 4 + ci;
        const float4* plane = xb + (size_t)c * 4096;
        float4 m[4];
        m[0] = hasT ? plane[(h0 - 1) * 32 + lane] : z4;
        m[1] =        plane[h0       * 32 + lane];
        m[2] =        plane[(h0 + 1) * 32 + lane];
        m[3] = hasB ? plane[(h0 + 2) * 32 + lane] : z4;

        float lf[4], rg[4];
#pragma unroll
        for (int i = 0; i < 4; i++) {
            lf[i] = __shfl_up_sync(0xffffffffu, m[i].w, 1);
            rg[i] = __shfl_down_sync(0xffffffffu, m[i].x, 1);
            if (lane == 0)  lf[i] = 0.f;
            if (lane == 31) rg[i] = 0.f;
        }

        const float* wp = dws + c * 12;
        float4 wA = *(const float4*)(wp);       // w00 w01 w02 w10
        float4 wB = *(const float4*)(wp + 4);   // w11 w12 w20 w21
        float  w8 = wp[8];                      // w22

#pragma unroll
        for (int row = 0; row < 2; row++) {
            float a0 = 0.f, a1 = 0.f, a2 = 0.f, a3 = 0.f;
#pragma unroll
            for (int r = 0; r < 3; r++) {
                int i = row + r;
                float w0 = (r == 0) ? wA.x : (r == 1) ? wA.w : wB.z;
                float w1 = (r == 0) ? wA.y : (r == 1) ? wB.x : wB.w;
                float w2 = (r == 0) ? wA.z : (r == 1) ? wB.y : w8;
                a0 += w0 * lf[i]  + w1 * m[i].x + w2 * m[i].y;
                a1 += w0 * m[i].x + w1 * m[i].y + w2 * m[i].z;
                a2 += w0 * m[i].y + w1 * m[i].z + w2 * m[i].w;
                a3 += w0 * m[i].z + w1 * m[i].w + w2 * rg[i];
            }
            *(float4*)(ys + row * 8704 + c * 136 + 4 * lane) =
                make_float4(f2tf32(a0), f2tf32(a1), f2tf32(a2), f2tf32(a3));
        }
    }
    __syncthreads();

    // ---- tf32 MMA pointwise: warp -> (row, mt, nb); M32 x N32 tile ----
    int row = wid >> 3, mt = (wid >> 2) & 1, nb = wid & 3;
    int ob = mt * 32, wbase = nb * 32;
    int g = lane >> 2, t4 = lane & 3;
    const float* ysr = ys + row * 8704;

    float acc[2][4][4];
#pragma unroll
    for (int ms = 0; ms < 2; ms++)
#pragma unroll
        for (int n = 0; n < 4; n++)
#pragma unroll
            for (int j = 0; j < 4; j++) acc[ms][n][j] = 0.f;

#pragma unroll 2
    for (int k = 0; k < 8; k++) {
        int k0 = 8 * k;
        uint32_t a[2][4];
#pragma unroll
        for (int ms = 0; ms < 2; ms++) {
            const float* aR = pwS + (ob + 16 * ms + g) * 68 + k0 + t4;
            a[ms][0] = __float_as_uint(aR[0]);
            a[ms][2] = __float_as_uint(aR[4]);
            a[ms][1] = __float_as_uint(aR[8 * 68]);
            a[ms][3] = __float_as_uint(aR[8 * 68 + 4]);
        }
        const float* bR = ysr + (k0 + t4) * 136 + wbase + g;
#pragma unroll
        for (int n = 0; n < 4; n++) {
            uint32_t b0 = __float_as_uint(bR[8 * n]);
            uint32_t b1 = __float_as_uint(bR[4 * 136 + 8 * n]);
#pragma unroll
            for (int ms = 0; ms < 2; ms++) {
                asm("mma.sync.aligned.m16n8k8.row.col.f32.tf32.tf32.f32 "
                    "{%0,%1,%2,%3}, {%4,%5,%6,%7}, {%8,%9}, {%0,%1,%2,%3};"
                    : "+f"(acc[ms][n][0]), "+f"(acc[ms][n][1]),
                      "+f"(acc[ms][n][2]), "+f"(acc[ms][n][3])
                    : "r"(a[ms][0]), "r"(a[ms][1]), "r"(a[ms][2]), "r"(a[ms][3]),
                      "r"(b0), "r"(b1));
            }
        }
    }

    // ---- epilogue: +dbias, store, BN partial stats ----
    float* outb = out + (size_t)(b * 64) * 16384 + (size_t)(h0 + row) * 128;
    float sAcc[2][2], s2Acc[2][2];
#pragma unroll
    for (int ms = 0; ms < 2; ms++) {
        sAcc[ms][0] = 0.f; sAcc[ms][1] = 0.f;
        s2Acc[ms][0] = 0.f; s2Acc[ms][1] = 0.f;
    }

#pragma unroll
    for (int ms = 0; ms < 2; ms++) {
        int rLo = ob + 16 * ms + g;
        float dbLo = dbs[rLo], dbHi = dbs[rLo + 8];
        size_t oLo = (size_t)rLo * 16384;
        size_t oHi = (size_t)(rLo + 8) * 16384;
#pragma unroll
        for (int n = 0; n < 4; n++) {
            int w = wbase + 8 * n + 2 * t4;
            float v0 = acc[ms][n][0] + dbLo;
            float v1 = acc[ms][n][1] + dbLo;
            float v2 = acc[ms][n][2] + dbHi;
            float v3 = acc[ms][n][3] + dbHi;
            *(float2*)(outb + oLo + w) = make_float2(v0, v1);
            *(float2*)(outb + oHi + w) = make_float2(v2, v3);
            sAcc[ms][0]  += v0 + v1;            s2Acc[ms][0] += v0 * v0 + v1 * v1;
            sAcc[ms][1]  += v2 + v3;            s2Acc[ms][1] += v2 * v2 + v3 * v3;
        }
    }
#pragma unroll
    for (int off = 1; off <= 2; off <<= 1)
#pragma unroll
        for (int ms = 0; ms < 2; ms++)
#pragma unroll
            for (int hl = 0; hl < 2; hl++) {
                sAcc[ms][hl]  += __shfl_xor_sync(0xffffffffu, sAcc[ms][hl],  off);
                s2Acc[ms][hl] += __shfl_xor_sync(0xffffffffu, s2Acc[ms][hl], off);
            }
    if (t4 == 0) {
#pragma unroll
        for (int ms = 0; ms < 2; ms++)
#pragma unroll
            for (int hl = 0; hl < 2; hl++) {
                int o = ob + 16 * ms + 8 * hl + g;
                atomicAdd(&sst[o],      sAcc[ms][hl]);
                atomicAdd(&sst[64 + o], s2Acc[ms][hl]);
            }
    }

    __syncthreads();
    if (tid < 64)       atomicAdd(&gSum[tid],        (double)sst[tid]);
    else if (tid < 128) atomicAdd(&gSumSq[tid - 64], (double)sst[tid]);
}

// =================================================================================
// Kernel 4: finalize BN scale/shift
// =================================================================================
__global__ void k_finalize(const float* __restrict__ gamma,
                           const float* __restrict__ beta)
{
    int t = threadIdx.x;
    if (t < 64) {
        const double n = 524288.0;   // 32 * 128 * 128
        double mean = gSum[t] / n;
        double var  = gSumSq[t] / n - mean * mean;
        double inv  = 1.0 / sqrt(var + 1e-5);
        double g    = (double)gamma[t];
        gScale[t] = (float)(g * inv);
        gShift[t] = (float)((double)beta[t] - mean * g * inv);
    }
}

// =================================================================================
// Kernel 5: apply BN in place (streaming, float4, MLP=4)
// =================================================================================
__global__ void __launch_bounds__(256) k_bn(float* __restrict__ out) {
    int base = blockIdx.x * 1024 + threadIdx.x;
    float4 v[4];
    int idx[4];
#pragma unroll
    for (int j = 0; j < 4; j++) {
        idx[j] = base + 256 * j;
        v[j] = ((const float4*)out)[idx[j]];
    }
#pragma unroll
    for (int j = 0; j < 4; j++) {
        int o = (idx[j] >> 12) & 63;             // 4096 float4 per (b,o) plane
        float sc = gScale[o], sh = gShift[o];
        v[j].x = fmaf(v[j].x, sc, sh);
        v[j].y = fmaf(v[j].y, sc, sh);
        v[j].z = fmaf(v[j].z, sc, sh);
        v[j].w = fmaf(v[j].w, sc, sh);
        ((float4*)out)[idx[j]] = v[j];
    }
}

// =================================================================================
extern "C" void kernel_launch(void* const* d_in, const int* in_sizes, int n_in,
                              void* d_out, int out_size)
{
    const float* x      = (const float*)d_in[0];
    const float* cg_w1  = (const float*)d_in[1];
    const float* cg_b1  = (const float*)d_in[2];
    const float* cg_w2  = (const float*)d_in[3];
    const float* cg_b2  = (const float*)d_in[4];
    const float* wg_w   = (const float*)d_in[5];
    const float* wg_b   = (const float*)d_in[6];
    const float* pg_w   = (const float*)d_in[7];
    const float* pg_b   = (const float*)d_in[8];
    const float* bg_w   = (const float*)d_in[9];
    const float* bg_b   = (const float*)d_in[10];
    const float* bn_g   = (const float*)d_in[11];
    const float* bn_b   = (const float*)d_in[12];
    float* out = (float*)d_out;

    cudaFuncSetAttribute(k_main, cudaFuncAttributeMaxDynamicSharedMemorySize, 90880);

    k_zero<<<1, 64>>>();
    k_cond_sums<<<2048, 256>>>(x);
    k_gen<<<32, 256>>>(cg_w1, cg_b1, cg_w2, cg_b2, wg_w, wg_b, pg_w, pg_b, bg_w, bg_b);
    dim3 g3(64, 32);
    k_main<<<g3, 512, 90880>>>(x, out);
    k_finalize<<<1, 64>>>(bn_g, bn_b);
    k_bn<<<8192, 256>>>(out);
}

// round 8
// speedup vs baseline: 1.5359x; 1.0156x over previous
#include <cuda_runtime.h>
#include <cuda_fp16.h>
#include <cstdint>

typedef unsigned long long ull;

// ---------------- device scratch (no runtime allocation allowed) ----------------
__device__ float  gS[32 * 64 * 9];     // strided sums for cond conv
__device__ float  gDw[32 * 576];       // per-sample depthwise weights (fp32)
__device__ float  gPw[32 * 4096];      // per-sample pointwise weights [b][o][c], tf32-rounded
__device__ float  gDb[32 * 64];        // per-sample dynamic bias
__device__ double gSum[64], gSumSq[64];// BN statistics accumulators
__device__ float  gScale[64], gShift[64];
__device__ __half gOut16[32 * 64 * 16384];   // pre-BN intermediate (fp16, 67 MB)

__device__ __forceinline__ float f2tf32(float x) {
    uint32_t u;
    asm("cvt.rna.tf32.f32 %0, %1;" : "=r"(u) : "f"(x));
    return __uint_as_float(u);
}

// =================================================================================
// Kernel 0: zero stats (graph replays must be deterministic)
// =================================================================================
__global__ void k_zero() {
    int t = threadIdx.x;
    if (t < 64) { gSum[t] = 0.0; gSumSq[t] = 0.0; }
}

// =================================================================================
// Kernel 1: per-(b,c) 9 strided sums S[kh][kw] = sum_{oh,ow} x[2oh+kh, 2ow+kw]
// =================================================================================
__global__ void __launch_bounds__(256) k_cond_sums(const float* __restrict__ x) {
    int bc = blockIdx.x;                 // b*64 + c
    int t  = threadIdx.x;
    const float* base = x + (size_t)bc * 16384;

    int i  = t >> 1;                     // row 0..127
    int j0 = (t & 1) * 64;               // half-row
    const float4* row4 = (const float4*)(base + i * 128 + j0);

    float ca0 = 0.f, ca1 = 0.f, ca2 = 0.f;
#pragma unroll
    for (int k = 0; k < 16; k++) {
        float4 v = row4[k];
        int j = j0 + 4 * k;
        ca0 += v.x + ((j <= 122) ? v.z : 0.f);
        ca1 += v.y + ((j <= 122) ? v.w : 0.f);
        ca2 += ((j >= 2) ? v.x : 0.f) + v.z;
    }
    bool ev = ((i & 1) == 0);
    float f0 = (ev  && i <= 124) ? 1.f : 0.f;
    float f1 = (!ev && i <= 125) ? 1.f : 0.f;
    float f2 = (ev  && i >= 2)   ? 1.f : 0.f;

    float bins[9] = { f0*ca0, f0*ca1, f0*ca2,
                      f1*ca0, f1*ca1, f1*ca2,
                      f2*ca0, f2*ca1, f2*ca2 };
#pragma unroll
    for (int off = 16; off; off >>= 1)
#pragma unroll
        for (int k = 0; k < 9; k++)
            bins[k] += __shfl_down_sync(0xffffffffu, bins[k], off);

    __shared__ float red[8][9];
    int lane = t & 31, w = t >> 5;
    if (lane == 0)
#pragma unroll
        for (int k = 0; k < 9; k++) red[w][k] = bins[k];
    __syncthreads();
    if (t < 9) {
        float s = 0.f;
#pragma unroll
        for (int ww = 0; ww < 8; ww++) s += red[ww][t];
        gS[bc * 9 + t] = s;
    }
}

// =================================================================================
// Kernel 2: per-sample condition vector + dynamic weight generation (tiny GEMMs)
// =================================================================================
__global__ void __launch_bounds__(256) k_gen(
    const float* __restrict__ cg_w1, const float* __restrict__ cg_b1,
    const float* __restrict__ cg_w2, const float* __restrict__ cg_b2,
    const float* __restrict__ wg_w,  const float* __restrict__ wg_b,
    const float* __restrict__ pg_w,  const float* __restrict__ pg_b,
    const float* __restrict__ bg_w,  const float* __restrict__ bg_b)
{
    __shared__ float Ss[576];
    __shared__ float parts[256];
    __shared__ float c0[16];
    __shared__ float cond[16];

    int b = blockIdx.x;
    int t = threadIdx.x;

    for (int idx = t; idx < 576; idx += 256) Ss[idx] = gS[b * 576 + idx];
    __syncthreads();

    {
        int co = t >> 4, part = t & 15;
        const float* wrow = cg_w1 + co * 576 + part * 36;
        const float* srow = Ss + part * 36;
        float s = 0.f;
#pragma unroll
        for (int k = 0; k < 36; k++) s += wrow[k] * srow[k];
        parts[t] = s;
    }
    __syncthreads();
    if (t < 16) {
        float s = 0.f;
#pragma unroll
        for (int p = 0; p < 16; p++) s += parts[t * 16 + p];
        s = s * (1.0f / 3969.0f) + cg_b1[t];
        c0[t] = fmaxf(s, 0.f);
    }
    __syncthreads();
    if (t < 16) {
        float s = cg_b2[t];
#pragma unroll
        for (int i = 0; i < 16; i++) s += c0[i] * cg_w2[t * 16 + i];
        cond[t] = fmaxf(s, 0.f);
    }
    __syncthreads();

    for (int r = t; r < 576; r += 256) {
        float s = wg_b[r];
        const float* wr = wg_w + r * 16;
#pragma unroll
        for (int q = 0; q < 16; q++) s += cond[q] * wr[q];
        gDw[b * 576 + r] = fmaxf(s, 0.f);
    }
    // pointwise weights [b][o][c], pre-rounded to tf32 for the MMA path
    for (int r = t; r < 4096; r += 256) {
        float s = pg_b[r];
        const float* wr = pg_w + r * 16;
#pragma unroll
        for (int q = 0; q < 16; q++) s += cond[q] * wr[q];
        gPw[b * 4096 + r] = f2tf32(fmaxf(s, 0.f));
    }
    if (t < 64) {
        float s = bg_b[t];
        const float* wr = bg_w + t * 16;
#pragma unroll
        for (int q = 0; q < 16; q++) s += cond[q] * wr[q];
        gDb[b * 64 + t] = s;
    }
}

// =================================================================================
// Kernel 3: fused depthwise3x3 + tf32 MMA pointwise, HS=4 output rows per CTA.
//   1024 threads; 1 CTA/SM; grid (32, 32). Writes fp16 pre-BN tensor.
// smem (floats):
//   ys  [4 row][64 c][136]  offset 0       (34816 fl)
//   pwS [64 o][68]          offset 34816   (4352 fl)
//   dws [64 c][12]          offset 39168   (768 fl)
//   dbs [64]                offset 39936
//   sst [128]               offset 40000   -> 40128 fl = 160512 B
// Depthwise: warp w handles channels {2w, 2w+1}; loads 6 x-rows/channel,
//   computes 4 output rows, shuffles hoisted across rows.
// MMA: warp -> (row = wid>>3, mt = (wid>>2)&1, nb = wid&3); M32 x N32 per warp.
// =================================================================================
__global__ void __launch_bounds__(1024, 1) k_main(const float* __restrict__ x)
{
    extern __shared__ float sm[];
    float* ys  = sm;
    float* pwS = sm + 34816;
    float* dws = sm + 39168;
    float* dbs = sm + 39936;
    float* sst = sm + 40000;

    int tid  = threadIdx.x;
    int lane = tid & 31, wid = tid >> 5;
    int h0 = blockIdx.x * 4, b = blockIdx.y;

    // ---- stage per-sample dynamic weights into smem ----
    {
        const float* pwg = gPw + b * 4096;
#pragma unroll
        for (int k = 0; k < 4; k++) {
            int idx = tid + 1024 * k;
            int o = idx >> 6, c = idx & 63;
            pwS[o * 68 + c] = pwg[idx];
        }
        if (tid < 576) {
            int c = tid / 9, j = tid - 9 * c;
            dws[c * 12 + j] = gDw[b * 576 + tid];
        }
        if (tid >= 576 && tid < 640) dbs[tid - 576] = gDb[b * 64 + (tid - 576)];
        if (tid >= 640 && tid < 768) sst[tid - 640] = 0.f;
    }
    __syncthreads();

    // ---- depthwise 3x3 (pad=1); warp w: channels {2w, 2w+1}; 4 output rows ----
    const float4* xb = (const float4*)(x + (size_t)b * 64 * 16384);
    const float4 z4 = make_float4(0.f, 0.f, 0.f, 0.f);

#pragma unroll
    for (int ci = 0; ci < 2; ci++) {
        int c = wid * 2 + ci;
        const float4* plane = xb + (size_t)c * 4096;

        float4 m[6];
        float lf[6], rg[6];
#pragma unroll
        for (int i = 0; i < 6; i++) {
            int gh = h0 - 1 + i;
            m[i] = ((unsigned)gh < 128u) ? plane[gh * 32 + lane] : z4;
        }
#pragma unroll
        for (int i = 0; i < 6; i++) {
            lf[i] = __shfl_up_sync(0xffffffffu, m[i].w, 1);
            rg[i] = __shfl_down_sync(0xffffffffu, m[i].x, 1);
            if (lane == 0)  lf[i] = 0.f;
            if (lane == 31) rg[i] = 0.f;
        }

        const float* wp = dws + c * 12;
        float4 wA = *(const float4*)(wp);       // w00 w01 w02 w10
        float4 wB = *(const float4*)(wp + 4);   // w11 w12 w20 w21
        float  w8 = wp[8];                      // w22

#pragma unroll
        for (int row = 0; row < 4; row++) {
            float a0 = 0.f, a1 = 0.f, a2 = 0.f, a3 = 0.f;
#pragma unroll
            for (int r = 0; r < 3; r++) {
                int i = row + r;
                float w0 = (r == 0) ? wA.x : (r == 1) ? wA.w : wB.z;
                float w1 = (r == 0) ? wA.y : (r == 1) ? wB.x : wB.w;
                float w2 = (r == 0) ? wA.z : (r == 1) ? wB.y : w8;
                a0 += w0 * lf[i]  + w1 * m[i].x + w2 * m[i].y;
                a1 += w0 * m[i].x + w1 * m[i].y + w2 * m[i].z;
                a2 += w0 * m[i].y + w1 * m[i].z + w2 * m[i].w;
                a3 += w0 * m[i].z + w1 * m[i].w + w2 * rg[i];
            }
            *(float4*)(ys + row * 8704 + c * 136 + 4 * lane) =
                make_float4(f2tf32(a0), f2tf32(a1), f2tf32(a2), f2tf32(a3));
        }
    }
    __syncthreads();

    // ---- tf32 MMA pointwise: warp -> (row, mt, nb); M32 x N32 tile ----
    int row = wid >> 3, mt = (wid >> 2) & 1, nb = wid & 3;
    int ob = mt * 32, wbase = nb * 32;
    int g = lane >> 2, t4 = lane & 3;
    const float* ysr = ys + row * 8704;

    float acc[2][4][4];
#pragma unroll
    for (int ms = 0; ms < 2; ms++)
#pragma unroll
        for (int n = 0; n < 4; n++)
#pragma unroll
            for (int j = 0; j < 4; j++) acc[ms][n][j] = 0.f;

#pragma unroll 2
    for (int k = 0; k < 8; k++) {
        int k0 = 8 * k;
        uint32_t a[2][4];
#pragma unroll
        for (int ms = 0; ms < 2; ms++) {
            const float* aR = pwS + (ob + 16 * ms + g) * 68 + k0 + t4;
            a[ms][0] = __float_as_uint(aR[0]);
            a[ms][2] = __float_as_uint(aR[4]);
            a[ms][1] = __float_as_uint(aR[8 * 68]);
            a[ms][3] = __float_as_uint(aR[8 * 68 + 4]);
        }
        const float* bR = ysr + (k0 + t4) * 136 + wbase + g;
#pragma unroll
        for (int n = 0; n < 4; n++) {
            uint32_t b0 = __float_as_uint(bR[8 * n]);
            uint32_t b1 = __float_as_uint(bR[4 * 136 + 8 * n]);
#pragma unroll
            for (int ms = 0; ms < 2; ms++) {
                asm("mma.sync.aligned.m16n8k8.row.col.f32.tf32.tf32.f32 "
                    "{%0,%1,%2,%3}, {%4,%5,%6,%7}, {%8,%9}, {%0,%1,%2,%3};"
                    : "+f"(acc[ms][n][0]), "+f"(acc[ms][n][1]),
                      "+f"(acc[ms][n][2]), "+f"(acc[ms][n][3])
                    : "r"(a[ms][0]), "r"(a[ms][1]), "r"(a[ms][2]), "r"(a[ms][3]),
                      "r"(b0), "r"(b1));
            }
        }
    }

    // ---- epilogue: +dbias, store fp16, BN partial stats (fp32) ----
    __half* outb = gOut16 + (size_t)(b * 64) * 16384 + (size_t)(h0 + row) * 128;
    float sAcc[2][2], s2Acc[2][2];
#pragma unroll
    for (int ms = 0; ms < 2; ms++) {
        sAcc[ms][0] = 0.f; sAcc[ms][1] = 0.f;
        s2Acc[ms][0] = 0.f; s2Acc[ms][1] = 0.f;
    }

#pragma unroll
    for (int ms = 0; ms < 2; ms++) {
        int rLo = ob + 16 * ms + g;
        float dbLo = dbs[rLo], dbHi = dbs[rLo + 8];
        size_t oLo = (size_t)rLo * 16384;
        size_t oHi = (size_t)(rLo + 8) * 16384;
#pragma unroll
        for (int n = 0; n < 4; n++) {
            int w = wbase + 8 * n + 2 * t4;
            float v0 = acc[ms][n][0] + dbLo;
            float v1 = acc[ms][n][1] + dbLo;
            float v2 = acc[ms][n][2] + dbHi;
            float v3 = acc[ms][n][3] + dbHi;
            *(__half2*)(outb + oLo + w) = __floats2half2_rn(v0, v1);
            *(__half2*)(outb + oHi + w) = __floats2half2_rn(v2, v3);
            sAcc[ms][0]  += v0 + v1;            s2Acc[ms][0] += v0 * v0 + v1 * v1;
            sAcc[ms][1]  += v2 + v3;            s2Acc[ms][1] += v2 * v2 + v3 * v3;
        }
    }
#pragma unroll
    for (int off = 1; off <= 2; off <<= 1)
#pragma unroll
        for (int ms = 0; ms < 2; ms++)
#pragma unroll
            for (int hl = 0; hl < 2; hl++) {
                sAcc[ms][hl]  += __shfl_xor_sync(0xffffffffu, sAcc[ms][hl],  off);
                s2Acc[ms][hl] += __shfl_xor_sync(0xffffffffu, s2Acc[ms][hl], off);
            }
    if (t4 == 0) {
#pragma unroll
        for (int ms = 0; ms < 2; ms++)
#pragma unroll
            for (int hl = 0; hl < 2; hl++) {
                int o = ob + 16 * ms + 8 * hl + g;
                atomicAdd(&sst[o],      sAcc[ms][hl]);
                atomicAdd(&sst[64 + o], s2Acc[ms][hl]);
            }
    }

    __syncthreads();
    if (tid < 64)       atomicAdd(&gSum[tid],        (double)sst[tid]);
    else if (tid < 128) atomicAdd(&gSumSq[tid - 64], (double)sst[tid]);
}

// =================================================================================
// Kernel 4: finalize BN scale/shift
// =================================================================================
__global__ void k_finalize(const float* __restrict__ gamma,
                           const float* __restrict__ beta)
{
    int t = threadIdx.x;
    if (t < 64) {
        const double n = 524288.0;   // 32 * 128 * 128
        double mean = gSum[t] / n;
        double var  = gSumSq[t] / n - mean * mean;
        double inv  = 1.0 / sqrt(var + 1e-5);
        double g    = (double)gamma[t];
        gScale[t] = (float)(g * inv);
        gShift[t] = (float)((double)beta[t] - mean * g * inv);
    }
}

// =================================================================================
// Kernel 5: apply BN (read fp16 scratch, write f32 out; MLP=4)
// =================================================================================
__global__ void __launch_bounds__(256) k_bn(float* __restrict__ out) {
    int base = blockIdx.x * 1024 + threadIdx.x;
    const uint2* src = (const uint2*)gOut16;     // 4 halves per uint2 == 1 float4 slot
#pragma unroll
    for (int j = 0; j < 4; j++) {
        int idx = base + 256 * j;
        uint2 raw = src[idx];
        __half2 hA = *(__half2*)&raw.x;
        __half2 hB = *(__half2*)&raw.y;
        float2 fA = __half22float2(hA);
        float2 fB = __half22float2(hB);
        int o = (idx >> 12) & 63;                // 4096 float4 per (b,o) plane
        float sc = gScale[o], sh = gShift[o];
        float4 v;
        v.x = fmaf(fA.x, sc, sh);
        v.y = fmaf(fA.y, sc, sh);
        v.z = fmaf(fB.x, sc, sh);
        v.w = fmaf(fB.y, sc, sh);
        ((float4*)out)[idx] = v;
    }
}

// =================================================================================
extern "C" void kernel_launch(void* const* d_in, const int* in_sizes, int n_in,
                              void* d_out, int out_size)
{
    const float* x      = (const float*)d_in[0];
    const float* cg_w1  = (const float*)d_in[1];
    const float* cg_b1  = (const float*)d_in[2];
    const float* cg_w2  = (const float*)d_in[3];
    const float* cg_b2  = (const float*)d_in[4];
    const float* wg_w   = (const float*)d_in[5];
    const float* wg_b   = (const float*)d_in[6];
    const float* pg_w   = (const float*)d_in[7];
    const float* pg_b   = (const float*)d_in[8];
    const float* bg_w   = (const float*)d_in[9];
    const float* bg_b   = (const float*)d_in[10];
    const float* bn_g   = (const float*)d_in[11];
    const float* bn_b   = (const float*)d_in[12];
    float* out = (float*)d_out;

    cudaFuncSetAttribute(k_main, cudaFuncAttributeMaxDynamicSharedMemorySize, 160512);

    k_zero<<<1, 64>>>();
    k_cond_sums<<<2048, 256>>>(x);
    k_gen<<<32, 256>>>(cg_w1, cg_b1, cg_w2, cg_b2, wg_w, wg_b, pg_w, pg_b, bg_w, bg_b);
    dim3 g3(32, 32);
    k_main<<<g3, 1024, 160512>>>(x);
    k_finalize<<<1, 64>>>(bn_g, bn_b);
    k_bn<<<8192, 256>>>(out);
}